// round 5
// baseline (speedup 1.0000x reference)
#include <cuda_runtime.h>
#include <cuda_fp16.h>
#include <cstdint>

#define NMAX 100000
#define NHALF 50000
#define HWORDS ((NMAX + 1) / 2)  // packed uint16x2 degree words

// Scratch (device globals; 16B-aligned for vectorized staging)
__device__ uint32_t g_degpack[HWORDS];
__device__ float    g_dinv[NMAX];
__device__ __align__(16) __half   g_p[NMAX];   // 200 KB: fits in one block's smem
__device__ float    g_t[NMAX];
__device__ __align__(16) __half2  g_rh[NMAX];  // 400 KB: staged in 200 KB halves
__device__ float2   g_acc[NMAX];

__device__ __forceinline__ void red_add_f32(float* addr, float v) {
    asm volatile("red.global.add.f32 [%0], %1;" :: "l"(addr), "f"(v) : "memory");
}
__device__ __forceinline__ void red_add_v2(float2* addr, float x, float y) {
    asm volatile("red.global.add.v2.f32 [%0], {%1, %2};"
                 :: "l"(addr), "f"(x), "f"(y) : "memory");
}

// ---------------- node kernels ----------------

__global__ void k_init() {
    int i = blockIdx.x * blockDim.x + threadIdx.x;
    if (i < HWORDS) g_degpack[i] = 0u;
}

__global__ void k_node1(const float* __restrict__ x, int n) {
    int i = blockIdx.x * blockDim.x + threadIdx.x;
    if (i < n) {
        uint32_t pack = g_degpack[i >> 1];
        uint32_t cnt = (pack >> ((i & 1) * 16)) & 0xFFFFu;
        float d = rsqrtf(1.0f + (float)cnt);   // +1 = self-loop
        g_dinv[i] = d;
        float p = d * x[i];
        g_p[i] = __float2half(p);
        g_t[i] = p;  // self-loop term (full precision)
    }
}

__global__ void k_node2(const float* __restrict__ W1, const float* __restrict__ b1,
                        const float* __restrict__ W2, int n) {
    int i = blockIdx.x * blockDim.x + threadIdx.x;
    if (i < n) {
        float dv = g_dinv[i];
        float s = dv * g_t[i];  // layer-1 aggregated scalar
        float g0 = 0.0f, g1 = 0.0f;
        #pragma unroll
        for (int j = 0; j < 16; j++) {
            float h = fmaxf(fmaf(s, __ldg(&W1[j]), __ldg(&b1[j])), 0.0f);
            g0 = fmaf(h, __ldg(&W2[2 * j + 0]), g0);
            g1 = fmaf(h, __ldg(&W2[2 * j + 1]), g1);
        }
        float2 r = make_float2(dv * g0, dv * g1);
        g_rh[i] = __float22half2_rn(r);
        g_acc[i] = r;  // self-loop term stays fp32
    }
}

__global__ void k_out(const float* __restrict__ b2, float* __restrict__ out, int n) {
    int i = blockIdx.x * blockDim.x + threadIdx.x;
    if (i < n) {
        float dv = g_dinv[i];
        float2 a = g_acc[i];
        float z0 = fmaf(dv, a.x, __ldg(&b2[0]));
        float z1 = fmaf(dv, a.y, __ldg(&b2[1]));
        float m = fmaxf(z0, z1);
        float lse = m + logf(expf(z0 - m) + expf(z1 - m));
        out[2 * i + 0] = z0 - lse;
        out[2 * i + 1] = z1 - lse;
    }
}

// -------- degree: smem-privatized packed histogram ----

__global__ void k_deg(const int* __restrict__ dst, int E) {
    extern __shared__ uint32_t hist[];  // HWORDS words = 200KB
    for (int i = threadIdx.x; i < HWORDS; i += blockDim.x) hist[i] = 0u;
    __syncthreads();

    int e8 = E >> 3;
    int stride = gridDim.x * blockDim.x;
    for (int i = blockIdx.x * blockDim.x + threadIdx.x; i < e8; i += stride) {
        int4 a = __ldcg(reinterpret_cast<const int4*>(dst) + 2 * i);
        int4 b = __ldcg(reinterpret_cast<const int4*>(dst) + 2 * i + 1);
        atomicAdd(&hist[a.x >> 1], 1u << ((a.x & 1) * 16));
        atomicAdd(&hist[a.y >> 1], 1u << ((a.y & 1) * 16));
        atomicAdd(&hist[a.z >> 1], 1u << ((a.z & 1) * 16));
        atomicAdd(&hist[a.w >> 1], 1u << ((a.w & 1) * 16));
        atomicAdd(&hist[b.x >> 1], 1u << ((b.x & 1) * 16));
        atomicAdd(&hist[b.y >> 1], 1u << ((b.y & 1) * 16));
        atomicAdd(&hist[b.z >> 1], 1u << ((b.z & 1) * 16));
        atomicAdd(&hist[b.w >> 1], 1u << ((b.w & 1) * 16));
    }
    if (blockIdx.x == 0) {  // tail
        for (int e = (e8 << 3) + (int)threadIdx.x; e < E; e += blockDim.x) {
            int d = dst[e];
            atomicAdd(&hist[d >> 1], 1u << ((d & 1) * 16));
        }
    }
    __syncthreads();

    for (int i = threadIdx.x; i < HWORDS; i += blockDim.x) {
        uint32_t v = hist[i];
        if (v) atomicAdd(&g_degpack[i], v);
    }
}

// ------- layer-1 aggregation: full p array staged in smem, RED to global ----

__global__ void k_agg1(const int* __restrict__ src, const int* __restrict__ dst, int E) {
    extern __shared__ __half sp[];  // 100k halves = 200 KB
    {
        const uint4* gp4 = reinterpret_cast<const uint4*>(g_p);
        uint4* sp4 = reinterpret_cast<uint4*>(sp);
        for (int i = threadIdx.x; i < NMAX / 8; i += blockDim.x) sp4[i] = __ldg(&gp4[i]);
    }
    __syncthreads();

    int e8 = E >> 3;
    int stride = gridDim.x * blockDim.x;
    for (int i = blockIdx.x * blockDim.x + threadIdx.x; i < e8; i += stride) {
        int4 sa = __ldcg(reinterpret_cast<const int4*>(src) + 2 * i);
        int4 sb = __ldcg(reinterpret_cast<const int4*>(src) + 2 * i + 1);
        int4 da = __ldcg(reinterpret_cast<const int4*>(dst) + 2 * i);
        int4 db = __ldcg(reinterpret_cast<const int4*>(dst) + 2 * i + 1);
        red_add_f32(&g_t[da.x], __half2float(sp[sa.x]));
        red_add_f32(&g_t[da.y], __half2float(sp[sa.y]));
        red_add_f32(&g_t[da.z], __half2float(sp[sa.z]));
        red_add_f32(&g_t[da.w], __half2float(sp[sa.w]));
        red_add_f32(&g_t[db.x], __half2float(sp[sb.x]));
        red_add_f32(&g_t[db.y], __half2float(sp[sb.y]));
        red_add_f32(&g_t[db.z], __half2float(sp[sb.z]));
        red_add_f32(&g_t[db.w], __half2float(sp[sb.w]));
    }
    if (blockIdx.x == 0) {  // tail
        for (int e = (e8 << 3) + (int)threadIdx.x; e < E; e += blockDim.x)
            red_add_f32(&g_t[dst[e]], __half2float(sp[src[e]]));
    }
}

// ------- layer-2 aggregation: 2 src-range passes, r-half staged in smem -----

__global__ void k_agg2(const int* __restrict__ src, const int* __restrict__ dst,
                       int E, int lo) {
    extern __shared__ __half2 sr[];  // 50k half2 = 200 KB
    {
        const uint4* gr4 = reinterpret_cast<const uint4*>(g_rh + lo);
        uint4* sr4 = reinterpret_cast<uint4*>(sr);
        for (int i = threadIdx.x; i < NHALF / 4; i += blockDim.x) sr4[i] = __ldg(&gr4[i]);
    }
    __syncthreads();

    int hi = lo + NHALF;
    int e8 = E >> 3;
    int stride = gridDim.x * blockDim.x;
    for (int i = blockIdx.x * blockDim.x + threadIdx.x; i < e8; i += stride) {
        int4 sa = __ldcg(reinterpret_cast<const int4*>(src) + 2 * i);
        int4 sb = __ldcg(reinterpret_cast<const int4*>(src) + 2 * i + 1);
        int4 da = __ldcg(reinterpret_cast<const int4*>(dst) + 2 * i);
        int4 db = __ldcg(reinterpret_cast<const int4*>(dst) + 2 * i + 1);
        int s[8] = {sa.x, sa.y, sa.z, sa.w, sb.x, sb.y, sb.z, sb.w};
        int d[8] = {da.x, da.y, da.z, da.w, db.x, db.y, db.z, db.w};
        #pragma unroll
        for (int j = 0; j < 8; j++) {
            if (s[j] >= lo && s[j] < hi) {
                float2 r = __half22float2(sr[s[j] - lo]);
                red_add_v2(&g_acc[d[j]], r.x, r.y);
            }
        }
    }
    if (blockIdx.x == 0) {  // tail
        for (int e = (e8 << 3) + (int)threadIdx.x; e < E; e += blockDim.x) {
            int sv = src[e];
            if (sv >= lo && sv < hi) {
                float2 r = __half22float2(sr[sv - lo]);
                red_add_v2(&g_acc[dst[e]], r.x, r.y);
            }
        }
    }
}

// ---------------- launch ----------------

extern "C" void kernel_launch(void* const* d_in, const int* in_sizes, int n_in,
                              void* d_out, int out_size) {
    const float* x  = (const float*)d_in[0];
    const int*   ei = (const int*)  d_in[1];
    const float* W1 = (const float*)d_in[2];
    const float* b1 = (const float*)d_in[3];
    const float* W2 = (const float*)d_in[4];
    const float* b2 = (const float*)d_in[5];
    int n = in_sizes[0];        // x is [N, 1]
    int E = in_sizes[1] / 2;    // edge_index is [2, E]
    const int* src = ei;
    const int* dst = ei + E;

    const int STAGE_BYTES = 200000;  // 200 KB (hist / p / r-half)
    cudaFuncSetAttribute(k_deg,  cudaFuncAttributeMaxDynamicSharedMemorySize, STAGE_BYTES);
    cudaFuncSetAttribute(k_agg1, cudaFuncAttributeMaxDynamicSharedMemorySize, STAGE_BYTES);
    cudaFuncSetAttribute(k_agg2, cudaFuncAttributeMaxDynamicSharedMemorySize, STAGE_BYTES);

    const int TB = 256;
    int nb_n = (n + TB - 1) / TB;
    int nb_h = (HWORDS + TB - 1) / TB;

    k_init <<<nb_h, TB>>>();
    k_deg  <<<148, 1024, STAGE_BYTES>>>(dst, E);
    k_node1<<<nb_n, TB>>>(x, n);
    k_agg1 <<<148, 1024, STAGE_BYTES>>>(src, dst, E);
    k_node2<<<nb_n, TB>>>(W1, b1, W2, n);
    k_agg2 <<<148, 1024, STAGE_BYTES>>>(src, dst, E, 0);
    k_agg2 <<<148, 1024, STAGE_BYTES>>>(src, dst, E, NHALF);
    k_out  <<<nb_n, TB>>>(b2, (float*)d_out, n);
}